// round 10
// baseline (speedup 1.0000x reference)
#include <cuda_runtime.h>

// SparseCoreAttention: B=2,H=12,N=2048,D=128,W=64
// out[bh,n,:] = softmax( (q[bh,n,:] . k[bh,col_ids[n,w],:]) / sqrt(D) ) @ v[bh,col_ids[n,w],:]
//
// One warp per query row. Lanes own 4-float d-slices so every k/v gather is a
// warp-coalesced 512B burst. Scores for 32 columns are reduced with a
// halving butterfly (31 shuffles for 32 column sums; lane l ends with col l).

#define NN 2048
#define DD 128
#define WW 64
#define BH 24                 // B*H
#define WARPS_PER_BLOCK 8
#define THREADS_PER_BLOCK 256

static __device__ __forceinline__ float score_batch32(
    const float* __restrict__ kb,      // k base for this (b,h): k + bh*N*D
    const int*   __restrict__ cols,    // 32 column ids (shared, broadcast reads)
    float4 qv, int lane)
{
    float part[32];
    const int doff = lane * 4;
#pragma unroll
    for (int w = 0; w < 32; w++) {
        const int c = cols[w];
        const float4 kk = *reinterpret_cast<const float4*>(kb + c * DD + doff);
        part[w] = fmaf(qv.x, kk.x, fmaf(qv.y, kk.y, fmaf(qv.z, kk.z, qv.w * kk.w)));
    }
    // Halving butterfly: after step with offset o, lane holds o partial sums for
    // the columns whose bit log2(o) matches the lane's. Ends with part[0] = score[lane].
#pragma unroll
    for (int o = 16; o >= 1; o >>= 1) {
        const bool up = (lane & o) != 0;
#pragma unroll
        for (int i = 0; i < o; i++) {
            const float a = part[i];
            const float b = part[i + o];
            const float send = up ? a : b;
            const float recv = __shfl_xor_sync(0xffffffffu, send, o);
            part[i] = (up ? b : a) + recv;
        }
    }
    return part[0];
}

__global__ __launch_bounds__(THREADS_PER_BLOCK)
void sparse_core_attention_kernel(
    const float* __restrict__ q,
    const float* __restrict__ k,
    const float* __restrict__ v,
    const int*   __restrict__ col_ids,
    float*       __restrict__ out)
{
    __shared__ int   sh_cols[WARPS_PER_BLOCK][WW];
    __shared__ float sh_e[WARPS_PER_BLOCK][WW];

    const int warp = threadIdx.x >> 5;
    const int lane = threadIdx.x & 31;
    const int gw   = blockIdx.x * WARPS_PER_BLOCK + warp;  // flat row id = bh*N + n
    const int n    = gw & (NN - 1);
    const int bh   = gw >> 11;

    const int doff = lane * 4;

    // q slice for this lane (coalesced float4)
    const float4 qv = *reinterpret_cast<const float4*>(q + (size_t)gw * DD + doff);

    // stage this row's 64 column ids into shared
    const int* crow = col_ids + n * WW;
    sh_cols[warp][lane]      = crow[lane];
    sh_cols[warp][lane + 32] = crow[lane + 32];
    __syncwarp();

    const float* kb = k + (size_t)bh * (NN * DD);
    const float* vb = v + (size_t)bh * (NN * DD);

    // ---- scores: two batches of 32 columns; lane ends with score[lane], score[lane+32]
    float s0 = score_batch32(kb, &sh_cols[warp][0],  qv, lane);
    float s1 = score_batch32(kb, &sh_cols[warp][32], qv, lane);

    const float SCALE = 0.08838834764831845f;   // 1/sqrt(128)
    s0 *= SCALE;
    s1 *= SCALE;

    // ---- softmax over 64 values (2 per lane)
    float m = fmaxf(s0, s1);
#pragma unroll
    for (int o = 16; o >= 1; o >>= 1)
        m = fmaxf(m, __shfl_xor_sync(0xffffffffu, m, o));

    const float e0 = __expf(s0 - m);
    const float e1 = __expf(s1 - m);
    float ssum = e0 + e1;
#pragma unroll
    for (int o = 16; o >= 1; o >>= 1)
        ssum += __shfl_xor_sync(0xffffffffu, ssum, o);
    const float inv = __fdividef(1.0f, ssum);

    // stage unnormalized weights; normalize the accumulated output at the end
    sh_e[warp][lane]      = e0;
    sh_e[warp][lane + 32] = e1;
    __syncwarp();

    // ---- PV: coalesced v gathers, broadcast weight from shared
    float4 acc = make_float4(0.f, 0.f, 0.f, 0.f);
#pragma unroll 16
    for (int w = 0; w < WW; w++) {
        const float p = sh_e[warp][w];
        const int   c = sh_cols[warp][w];
        const float4 vv = *reinterpret_cast<const float4*>(vb + c * DD + doff);
        acc.x = fmaf(p, vv.x, acc.x);
        acc.y = fmaf(p, vv.y, acc.y);
        acc.z = fmaf(p, vv.z, acc.z);
        acc.w = fmaf(p, vv.w, acc.w);
    }
    acc.x *= inv; acc.y *= inv; acc.z *= inv; acc.w *= inv;

    *reinterpret_cast<float4*>(out + (size_t)gw * DD + doff) = acc;
}

extern "C" void kernel_launch(void* const* d_in, const int* in_sizes, int n_in,
                              void* d_out, int out_size)
{
    const float* q   = (const float*)d_in[0];
    const float* k   = (const float*)d_in[1];
    const float* v   = (const float*)d_in[2];
    const int*   col = (const int*)d_in[3];
    float*       out = (float*)d_out;

    const int total_warps = BH * NN;                       // 49152 rows
    const int blocks = total_warps / WARPS_PER_BLOCK;      // 6144
    sparse_core_attention_kernel<<<blocks, THREADS_PER_BLOCK>>>(q, k, v, col, out);
}

// round 11
// speedup vs baseline: 1.0818x; 1.0818x over previous
#include <cuda_runtime.h>
#include <cuda_fp16.h>

// SparseCoreAttention: B=2,H=12,N=2048,D=128,W=64
// R10: k/v converted once to fp16 scratch (__device__ globals) -> gather bytes
// halved (L1/L2 were the binding pipes at 86.6%/76.8%). Dot products and PV
// accumulate in fp32 from fp16 operands (rel_err budget ~6e-4 < 1e-3).

#define NN 2048
#define DD 128
#define WW 64
#define BH 24
#define WARPS_PER_BLOCK 8
#define THREADS_PER_BLOCK 256

#define TOT_ELEMS (BH * NN * DD)            // 6,291,456 per tensor
#define TOT_H2    (TOT_ELEMS / 2)           // half2 count
#define TOT_F4    (TOT_ELEMS / 4)           // float4 count

__device__ __half2 g_kh[TOT_H2];
__device__ __half2 g_vh[TOT_H2];

// ---- fp32 -> fp16 conversion (streaming, ~75MB traffic, ~10-15us) ----
__global__ __launch_bounds__(256)
void cvt_kernel(const float4* __restrict__ k4, const float4* __restrict__ v4)
{
    const int i = blockIdx.x * blockDim.x + threadIdx.x;   // < TOT_F4
    const float4 a = k4[i];
    const float4 b = v4[i];
    __half2 ka = __floats2half2_rn(a.x, a.y);
    __half2 kb = __floats2half2_rn(a.z, a.w);
    __half2 va = __floats2half2_rn(b.x, b.y);
    __half2 vb = __floats2half2_rn(b.z, b.w);
    uint2 ku, vu;
    ku.x = *reinterpret_cast<unsigned int*>(&ka);
    ku.y = *reinterpret_cast<unsigned int*>(&kb);
    vu.x = *reinterpret_cast<unsigned int*>(&va);
    vu.y = *reinterpret_cast<unsigned int*>(&vb);
    *reinterpret_cast<uint2*>(&g_kh[2 * i]) = ku;
    *reinterpret_cast<uint2*>(&g_vh[2 * i]) = vu;
}

// dot-partial for one gathered fp16 chunk (4 halves) against fp32 q slice
static __device__ __forceinline__ float dot4_h(const uint2 raw, const float4 qv)
{
    const __half2 h0 = *reinterpret_cast<const __half2*>(&raw.x);
    const __half2 h1 = *reinterpret_cast<const __half2*>(&raw.y);
    const float2 f0 = __half22float2(h0);
    const float2 f1 = __half22float2(h1);
    return fmaf(qv.x, f0.x, fmaf(qv.y, f0.y, fmaf(qv.z, f1.x, qv.w * f1.y)));
}

static __device__ __forceinline__ float score_batch32(
    const __half2* __restrict__ kb_lane,   // k base + bh offset + lane*2 (half2 units)
    const int*     __restrict__ cols,
    float4 qv, int lane)
{
    float part[32];
#pragma unroll
    for (int w = 0; w < 32; w++) {
        const int c = cols[w];
        const uint2 raw = *reinterpret_cast<const uint2*>(kb_lane + c * (DD / 2));
        part[w] = dot4_h(raw, qv);
    }
    // Halving butterfly: 31 shuffles reduce 32 chunk-partials so that
    // lane l ends holding the full dot product of column l.
#pragma unroll
    for (int o = 16; o >= 1; o >>= 1) {
        const bool up = (lane & o) != 0;
#pragma unroll
        for (int i = 0; i < o; i++) {
            const float a = part[i];
            const float b = part[i + o];
            const float send = up ? a : b;
            const float recv = __shfl_xor_sync(0xffffffffu, send, o);
            part[i] = (up ? b : a) + recv;
        }
    }
    return part[0];
}

__global__ __launch_bounds__(THREADS_PER_BLOCK)
void sparse_core_attention_kernel(
    const float* __restrict__ q,
    const int*   __restrict__ col_ids,
    float*       __restrict__ out)
{
    __shared__ int   sh_cols[WARPS_PER_BLOCK][WW];
    __shared__ float sh_e[WARPS_PER_BLOCK][WW];

    const int warp = threadIdx.x >> 5;
    const int lane = threadIdx.x & 31;
    const int gw   = blockIdx.x * WARPS_PER_BLOCK + warp;  // bh*N + n
    const int n    = gw & (NN - 1);
    const int bh   = gw >> 11;

    // q slice: 4 floats at d = lane*4 (coalesced float4)
    const float4 qv = *reinterpret_cast<const float4*>(q + (size_t)gw * DD + lane * 4);

    const int* crow = col_ids + n * WW;
    sh_cols[warp][lane]      = crow[lane];
    sh_cols[warp][lane + 32] = crow[lane + 32];
    __syncwarp();

    // lane-local bases: +lane*2 half2 = d offset lane*4
    const __half2* kb_lane = g_kh + (size_t)bh * (NN * DD / 2) + lane * 2;
    const __half2* vb_lane = g_vh + (size_t)bh * (NN * DD / 2) + lane * 2;

    float s0 = score_batch32(kb_lane, &sh_cols[warp][0],  qv, lane);
    float s1 = score_batch32(kb_lane, &sh_cols[warp][32], qv, lane);

    const float SCALE = 0.08838834764831845f;   // 1/sqrt(128)
    s0 *= SCALE;
    s1 *= SCALE;

    float m = fmaxf(s0, s1);
#pragma unroll
    for (int o = 16; o >= 1; o >>= 1)
        m = fmaxf(m, __shfl_xor_sync(0xffffffffu, m, o));

    const float e0 = __expf(s0 - m);
    const float e1 = __expf(s1 - m);
    float ssum = e0 + e1;
#pragma unroll
    for (int o = 16; o >= 1; o >>= 1)
        ssum += __shfl_xor_sync(0xffffffffu, ssum, o);
    const float inv = __fdividef(1.0f, ssum);

    sh_e[warp][lane]      = e0;
    sh_e[warp][lane + 32] = e1;
    __syncwarp();

    // PV: coalesced fp16 v gathers (256B/warp), broadcast weights from shared,
    // fp32 accumulation; normalize once at the end.
    float4 acc = make_float4(0.f, 0.f, 0.f, 0.f);
#pragma unroll 16
    for (int w = 0; w < WW; w++) {
        const float p = sh_e[warp][w];
        const int   c = sh_cols[warp][w];
        const uint2 raw = *reinterpret_cast<const uint2*>(vb_lane + c * (DD / 2));
        const __half2 h0 = *reinterpret_cast<const __half2*>(&raw.x);
        const __half2 h1 = *reinterpret_cast<const __half2*>(&raw.y);
        const float2 f0 = __half22float2(h0);
        const float2 f1 = __half22float2(h1);
        acc.x = fmaf(p, f0.x, acc.x);
        acc.y = fmaf(p, f0.y, acc.y);
        acc.z = fmaf(p, f1.x, acc.z);
        acc.w = fmaf(p, f1.y, acc.w);
    }
    acc.x *= inv; acc.y *= inv; acc.z *= inv; acc.w *= inv;

    *reinterpret_cast<float4*>(out + (size_t)gw * DD + lane * 4) = acc;
}

extern "C" void kernel_launch(void* const* d_in, const int* in_sizes, int n_in,
                              void* d_out, int out_size)
{
    const float* q   = (const float*)d_in[0];
    const float* k   = (const float*)d_in[1];
    const float* v   = (const float*)d_in[2];
    const int*   col = (const int*)d_in[3];
    float*       out = (float*)d_out;

    cvt_kernel<<<TOT_F4 / 256, 256>>>((const float4*)k, (const float4*)v);

    const int blocks = (BH * NN) / WARPS_PER_BLOCK;   // 6144
    sparse_core_attention_kernel<<<blocks, THREADS_PER_BLOCK>>>(q, col, out);
}

// round 12
// speedup vs baseline: 1.3043x; 1.2056x over previous
#include <cuda_runtime.h>
#include <cuda_fp16.h>

// SparseCoreAttention: B=2,H=12,N=2048,D=128,W=64
// R11: issue-bound (76.5% issue, fma+alu 85% of it) -> cut instructions:
//  - 2 columns per LDG.128 (half-warp per column): halves LDG/IMAD slots
//  - fp16 HMUL2/HFMA2 chunk dot (q quantized in-kernel), fp32 butterfly
//  - packed fma.rn.f32x2 in PV (FFMA2; fp32 accuracy, half the FMA ops)

#define NN 2048
#define DD 128
#define WW 64
#define BH 24
#define WARPS_PER_BLOCK 8
#define THREADS_PER_BLOCK 256

#define TOT_ELEMS (BH * NN * DD)
#define TOT_H2    (TOT_ELEMS / 2)
#define TOT_F4    (TOT_ELEMS / 4)

__device__ __half2 g_kh[TOT_H2];
__device__ __half2 g_vh[TOT_H2];

// ---- fp32 -> fp16 scratch conversion (streaming) ----
__global__ __launch_bounds__(256)
void cvt_kernel(const float4* __restrict__ k4, const float4* __restrict__ v4)
{
    const int i = blockIdx.x * blockDim.x + threadIdx.x;
    const float4 a = k4[i];
    const float4 b = v4[i];
    __half2 ka = __floats2half2_rn(a.x, a.y);
    __half2 kb = __floats2half2_rn(a.z, a.w);
    __half2 va = __floats2half2_rn(b.x, b.y);
    __half2 vb = __floats2half2_rn(b.z, b.w);
    uint2 ku, vu;
    ku.x = *reinterpret_cast<unsigned int*>(&ka);
    ku.y = *reinterpret_cast<unsigned int*>(&kb);
    vu.x = *reinterpret_cast<unsigned int*>(&va);
    vu.y = *reinterpret_cast<unsigned int*>(&vb);
    *reinterpret_cast<uint2*>(&g_kh[2 * i]) = ku;
    *reinterpret_cast<uint2*>(&g_vh[2 * i]) = vu;
}

// ---- packed f32x2 helpers (Blackwell FFMA2 path) ----
static __device__ __forceinline__ unsigned long long pk2(float x, float y)
{
    unsigned long long r;
    asm("mov.b64 %0, {%1, %2};" : "=l"(r) : "f"(x), "f"(y));
    return r;
}
static __device__ __forceinline__ void upk2(unsigned long long r, float& x, float& y)
{
    asm("mov.b64 {%0, %1}, %2;" : "=f"(x), "=f"(y) : "l"(r));
}
static __device__ __forceinline__ unsigned long long ffma2(
    unsigned long long a, unsigned long long b, unsigned long long c)
{
    unsigned long long d;
    asm("fma.rn.f32x2 %0, %1, %2, %3;" : "=l"(d) : "l"(a), "l"(b), "l"(c));
    return d;
}

// one butterfly step: 16-lane groups, array halves from 2*HALF to HALF
template <int O, int HALF>
static __device__ __forceinline__ void bstep(float* part, int j)
{
    const bool up = (j & O) != 0;
#pragma unroll
    for (int i = 0; i < HALF; i++) {
        const float a = part[i];
        const float b = part[i + HALF];
        const float send = up ? a : b;
        const float recv = __shfl_xor_sync(0xffffffffu, send, O);
        part[i] = (up ? b : a) + recv;
    }
}

__global__ __launch_bounds__(THREADS_PER_BLOCK)
void sparse_core_attention_kernel(
    const float* __restrict__ q,
    const int*   __restrict__ col_ids,
    float*       __restrict__ out)
{
    __shared__ int   sh_cols[WARPS_PER_BLOCK][WW];
    __shared__ float sh_e[WARPS_PER_BLOCK][WW];

    const int warp = threadIdx.x >> 5;
    const int lane = threadIdx.x & 31;
    const int gw   = blockIdx.x * WARPS_PER_BLOCK + warp;  // bh*N + n
    const int n    = gw & (NN - 1);
    const int bh   = gw >> 11;
    const int j    = lane & 15;      // d-chunk owner within half-warp
    const int h    = lane >> 4;      // which of the 2 columns per load

    // q chunk d = 8j..8j+7, converted to fp16 once per row
    const float* qrow = q + (size_t)gw * DD + 8 * j;
    const float4 qa = *reinterpret_cast<const float4*>(qrow);
    const float4 qb = *reinterpret_cast<const float4*>(qrow + 4);
    const __half2 q0 = __floats2half2_rn(qa.x, qa.y);
    const __half2 q1 = __floats2half2_rn(qa.z, qa.w);
    const __half2 q2 = __floats2half2_rn(qb.x, qb.y);
    const __half2 q3 = __floats2half2_rn(qb.z, qb.w);

    const int* crow = col_ids + n * WW;
    sh_cols[warp][lane]      = crow[lane];
    sh_cols[warp][lane + 32] = crow[lane + 32];
    __syncwarp();

    // fp16 row = 256B = 16 uint4; lane's chunk is uint4 index c*16 + j
    const uint4* kb4 = reinterpret_cast<const uint4*>(g_kh + (size_t)bh * (NN * DD / 2));
    const uint4* vb4 = reinterpret_cast<const uint4*>(g_vh + (size_t)bh * (NN * DD / 2));

    // ---- QK: iter w covers columns cols[2w] (h=0) and cols[2w+1] (h=1)
    float part[32];
#pragma unroll
    for (int w = 0; w < 32; w++) {
        const int c = sh_cols[warp][2 * w + h];
        const uint4 kk = kb4[c * 16 + j];
        const __half2 k0 = *reinterpret_cast<const __half2*>(&kk.x);
        const __half2 k1 = *reinterpret_cast<const __half2*>(&kk.y);
        const __half2 k2 = *reinterpret_cast<const __half2*>(&kk.z);
        const __half2 k3 = *reinterpret_cast<const __half2*>(&kk.w);
        __half2 t0 = __hmul2(k0, q0);
        t0 = __hfma2(k1, q1, t0);
        __half2 t1 = __hmul2(k2, q2);
        t1 = __hfma2(k3, q3, t1);
        const float2 f = __half22float2(__hadd2(t0, t1));
        part[w] = f.x + f.y;
    }

    // 4-step halving butterfly within each 16-lane group:
    // lane j ends with part[i] = full dot of column 4j + 2i + h (i in {0,1})
    bstep<8, 16>(part, j);
    bstep<4, 8>(part, j);
    bstep<2, 4>(part, j);
    bstep<1, 2>(part, j);

    const float SCALE = 0.08838834764831845f;   // 1/sqrt(128)
    const float s0 = part[0] * SCALE;            // column 4j + h
    const float s1 = part[1] * SCALE;            // column 4j + 2 + h

    // ---- softmax over all 64 (full-warp reduction, 2 values/lane)
    float m = fmaxf(s0, s1);
#pragma unroll
    for (int o = 16; o >= 1; o >>= 1)
        m = fmaxf(m, __shfl_xor_sync(0xffffffffu, m, o));

    const float e0 = __expf(s0 - m);
    const float e1 = __expf(s1 - m);
    float ssum = e0 + e1;
#pragma unroll
    for (int o = 16; o >= 1; o >>= 1)
        ssum += __shfl_xor_sync(0xffffffffu, ssum, o);
    const float inv = __fdividef(1.0f, ssum);

    const int idx0 = 4 * j + h;
    sh_e[warp][idx0]     = e0;
    sh_e[warp][idx0 + 2] = e1;
    __syncwarp();

    // ---- PV: 2 columns per LDG.128; lane accumulates d = 8j..8j+7 for its
    // half-warp's column set, fp32 packed FFMA2 accumulators.
    unsigned long long acc0 = 0ull, acc1 = 0ull, acc2 = 0ull, acc3 = 0ull;
#pragma unroll
    for (int w = 0; w < 32; w++) {
        const int wc = 2 * w + h;
        const float p = sh_e[warp][wc];
        const int   c = sh_cols[warp][wc];
        const uint4 vv = vb4[c * 16 + j];
        const unsigned long long pp = pk2(p, p);
        const float2 f0 = __half22float2(*reinterpret_cast<const __half2*>(&vv.x));
        const float2 f1 = __half22float2(*reinterpret_cast<const __half2*>(&vv.y));
        const float2 f2 = __half22float2(*reinterpret_cast<const __half2*>(&vv.z));
        const float2 f3 = __half22float2(*reinterpret_cast<const __half2*>(&vv.w));
        acc0 = ffma2(pk2(f0.x, f0.y), pp, acc0);
        acc1 = ffma2(pk2(f1.x, f1.y), pp, acc1);
        acc2 = ffma2(pk2(f2.x, f2.y), pp, acc2);
        acc3 = ffma2(pk2(f3.x, f3.y), pp, acc3);
    }

    float r0, r1, r2, r3, r4, r5, r6, r7;
    upk2(acc0, r0, r1);
    upk2(acc1, r2, r3);
    upk2(acc2, r4, r5);
    upk2(acc3, r6, r7);

    // cross-half-warp combine: lane keeps the 4 values it will store
    // (d = 8j + 4h + 0..3), exchanging only those across xor-16.
    float keep[4], other[4];
    if (h == 0) {
        keep[0] = r0; keep[1] = r1; keep[2] = r2; keep[3] = r3;
        other[0] = r4; other[1] = r5; other[2] = r6; other[3] = r7;
    } else {
        keep[0] = r4; keep[1] = r5; keep[2] = r6; keep[3] = r7;
        other[0] = r0; other[1] = r1; other[2] = r2; other[3] = r3;
    }
#pragma unroll
    for (int i = 0; i < 4; i++) {
        const float recv = __shfl_xor_sync(0xffffffffu, other[i], 16);
        keep[i] = (keep[i] + recv) * inv;
    }

    // warp writes 512B contiguously: lane (j,h) -> d = 8j + 4h
    float4 res = make_float4(keep[0], keep[1], keep[2], keep[3]);
    *reinterpret_cast<float4*>(out + (size_t)gw * DD + 8 * j + 4 * h) = res;
}

extern "C" void kernel_launch(void* const* d_in, const int* in_sizes, int n_in,
                              void* d_out, int out_size)
{
    const float* q   = (const float*)d_in[0];
    const float* k   = (const float*)d_in[1];
    const float* v   = (const float*)d_in[2];
    const int*   col = (const int*)d_in[3];
    float*       out = (float*)d_out;

    cvt_kernel<<<TOT_F4 / 256, 256>>>((const float4*)k, (const float4*)v);

    const int blocks = (BH * NN) / WARPS_PER_BLOCK;   // 6144
    sparse_core_attention_kernel<<<blocks, THREADS_PER_BLOCK>>>(q, col, out);
}

// round 13
// speedup vs baseline: 1.3373x; 1.0254x over previous
#include <cuda_runtime.h>
#include <cuda_fp16.h>

// SparseCoreAttention: B=2,H=12,N=2048,D=128,W=64
// R12: L1-wavefront bound (77.4%), ~100/370 wf per row were scalar LDS.
//  - parity-split col ids, int2 QK reads (16 LDS.64 vs 32 LDS.32)
//  - packed (col,e) uint4 pairs for PV (16 LDS.128 vs 64 LDS.32)
//  - __launch_bounds__(256,5) -> regs<=51, occ 32->40 warps/SM

#define NN 2048
#define DD 128
#define WW 64
#define BH 24
#define WARPS_PER_BLOCK 8
#define THREADS_PER_BLOCK 256

#define TOT_ELEMS (BH * NN * DD)
#define TOT_H2    (TOT_ELEMS / 2)
#define TOT_F4    (TOT_ELEMS / 4)

__device__ __half2 g_kh[TOT_H2];
__device__ __half2 g_vh[TOT_H2];

// ---- fp32 -> fp16 scratch conversion (streaming, near HBM peak) ----
__global__ __launch_bounds__(256)
void cvt_kernel(const float4* __restrict__ k4, const float4* __restrict__ v4)
{
    const int i = blockIdx.x * blockDim.x + threadIdx.x;
    const float4 a = k4[i];
    const float4 b = v4[i];
    __half2 ka = __floats2half2_rn(a.x, a.y);
    __half2 kb = __floats2half2_rn(a.z, a.w);
    __half2 va = __floats2half2_rn(b.x, b.y);
    __half2 vb = __floats2half2_rn(b.z, b.w);
    uint2 ku, vu;
    ku.x = *reinterpret_cast<unsigned int*>(&ka);
    ku.y = *reinterpret_cast<unsigned int*>(&kb);
    vu.x = *reinterpret_cast<unsigned int*>(&va);
    vu.y = *reinterpret_cast<unsigned int*>(&vb);
    *reinterpret_cast<uint2*>(&g_kh[2 * i]) = ku;
    *reinterpret_cast<uint2*>(&g_vh[2 * i]) = vu;
}

// ---- packed f32x2 helpers (Blackwell FFMA2) ----
static __device__ __forceinline__ unsigned long long pk2(float x, float y)
{
    unsigned long long r;
    asm("mov.b64 %0, {%1, %2};" : "=l"(r) : "f"(x), "f"(y));
    return r;
}
static __device__ __forceinline__ void upk2(unsigned long long r, float& x, float& y)
{
    asm("mov.b64 {%0, %1}, %2;" : "=f"(x), "=f"(y) : "l"(r));
}
static __device__ __forceinline__ unsigned long long ffma2(
    unsigned long long a, unsigned long long b, unsigned long long c)
{
    unsigned long long d;
    asm("fma.rn.f32x2 %0, %1, %2, %3;" : "=l"(d) : "l"(a), "l"(b), "l"(c));
    return d;
}

template <int O, int HALF>
static __device__ __forceinline__ void bstep(float* part, int j)
{
    const bool up = (j & O) != 0;
#pragma unroll
    for (int i = 0; i < HALF; i++) {
        const float a = part[i];
        const float b = part[i + HALF];
        const float send = up ? a : b;
        const float recv = __shfl_xor_sync(0xffffffffu, send, O);
        part[i] = (up ? b : a) + recv;
    }
}

// dot partial of one 16B fp16 chunk against fp16 q chunk (fp32 result)
static __device__ __forceinline__ float dot8_h(
    const uint4 kk, __half2 q0, __half2 q1, __half2 q2, __half2 q3)
{
    const __half2 k0 = *reinterpret_cast<const __half2*>(&kk.x);
    const __half2 k1 = *reinterpret_cast<const __half2*>(&kk.y);
    const __half2 k2 = *reinterpret_cast<const __half2*>(&kk.z);
    const __half2 k3 = *reinterpret_cast<const __half2*>(&kk.w);
    __half2 t0 = __hmul2(k0, q0);
    t0 = __hfma2(k1, q1, t0);
    __half2 t1 = __hmul2(k2, q2);
    t1 = __hfma2(k3, q3, t1);
    const float2 f = __half22float2(__hadd2(t0, t1));
    return f.x + f.y;
}

__global__ __launch_bounds__(THREADS_PER_BLOCK, 5)
void sparse_core_attention_kernel(
    const float* __restrict__ q,
    const int*   __restrict__ col_ids,
    float*       __restrict__ out)
{
    // parity-split col ids; packed (col, e, col, e) pairs for PV
    __shared__ int   sh_colp[WARPS_PER_BLOCK][2][32];
    __shared__ uint4 sh_pe[WARPS_PER_BLOCK][2][16];

    const int warp = threadIdx.x >> 5;
    const int lane = threadIdx.x & 31;
    const int gw   = blockIdx.x * WARPS_PER_BLOCK + warp;  // bh*N + n
    const int n    = gw & (NN - 1);
    const int bh   = gw >> 11;
    const int j    = lane & 15;      // d-chunk owner within half-warp
    const int h    = lane >> 4;      // parity (which of 2 columns per load)

    // q chunk d = 8j..8j+7, quantized to fp16 once
    const float* qrow = q + (size_t)gw * DD + 8 * j;
    const float4 qa = *reinterpret_cast<const float4*>(qrow);
    const float4 qb = *reinterpret_cast<const float4*>(qrow + 4);
    const __half2 q0 = __floats2half2_rn(qa.x, qa.y);
    const __half2 q1 = __floats2half2_rn(qa.z, qa.w);
    const __half2 q2 = __floats2half2_rn(qb.x, qb.y);
    const __half2 q3 = __floats2half2_rn(qb.z, qb.w);

    // stage col ids parity-split: lane l loads crow[2l], crow[2l+1]
    {
        const int2 cc = *reinterpret_cast<const int2*>(col_ids + n * WW + 2 * lane);
        sh_colp[warp][0][lane] = cc.x;
        sh_colp[warp][1][lane] = cc.y;
    }
    __syncwarp();

    const uint4* kb4 = reinterpret_cast<const uint4*>(g_kh + (size_t)bh * (NN * DD / 2));
    const uint4* vb4 = reinterpret_cast<const uint4*>(g_vh + (size_t)bh * (NN * DD / 2));

    // ---- QK: iter w handles column cols[2w+h]; col ids read as int2 pairs
    float part[32];
#pragma unroll
    for (int w2 = 0; w2 < 16; w2++) {
        const int2 cp = *reinterpret_cast<const int2*>(&sh_colp[warp][h][2 * w2]);
        const uint4 ka = kb4[cp.x * 16 + j];
        const uint4 kb = kb4[cp.y * 16 + j];
        part[2 * w2]     = dot8_h(ka, q0, q1, q2, q3);
        part[2 * w2 + 1] = dot8_h(kb, q0, q1, q2, q3);
    }

    // 4-step halving butterfly within 16-lane groups:
    // lane j ends with part[i] = dot of column 4j + 2i + h (i in {0,1})
    bstep<8, 16>(part, j);
    bstep<4, 8>(part, j);
    bstep<2, 4>(part, j);
    bstep<1, 2>(part, j);

    const float SCALE = 0.08838834764831845f;   // 1/sqrt(128)
    const float s0 = part[0] * SCALE;            // column 4j + h
    const float s1 = part[1] * SCALE;            // column 4j + 2 + h

    // ---- softmax over 64 (2 values/lane, full-warp reduction)
    float m = fmaxf(s0, s1);
#pragma unroll
    for (int o = 16; o >= 1; o >>= 1)
        m = fmaxf(m, __shfl_xor_sync(0xffffffffu, m, o));

    const float e0 = __expf(s0 - m);
    const float e1 = __expf(s1 - m);
    float ssum = e0 + e1;
#pragma unroll
    for (int o = 16; o >= 1; o >>= 1)
        ssum += __shfl_xor_sync(0xffffffffu, ssum, o);
    const float inv = __fdividef(1.0f, ssum);

    // lane (j,h) owns parity-h entries w = 2j (col 4j+h) and 2j+1 (col 4j+2+h):
    // pack (c0, e0, c1, e1) into one STS.128
    {
        const int c0 = sh_colp[warp][h][2 * j];
        const int c1 = sh_colp[warp][h][2 * j + 1];
        uint4 pe;
        pe.x = (unsigned)c0;
        pe.y = __float_as_uint(e0);
        pe.z = (unsigned)c1;
        pe.w = __float_as_uint(e1);
        sh_pe[warp][h][j] = pe;
    }
    __syncwarp();

    // ---- PV: one LDS.128 feeds 2 gather+FFMA2 iterations
    unsigned long long acc0 = 0ull, acc1 = 0ull, acc2 = 0ull, acc3 = 0ull;
#pragma unroll
    for (int wp = 0; wp < 16; wp++) {
        const uint4 P = sh_pe[warp][h][wp];
        {
            const uint4 vv = vb4[(int)P.x * 16 + j];
            const unsigned long long pp = pk2(__uint_as_float(P.y), __uint_as_float(P.y));
            const float2 f0 = __half22float2(*reinterpret_cast<const __half2*>(&vv.x));
            const float2 f1 = __half22float2(*reinterpret_cast<const __half2*>(&vv.y));
            const float2 f2 = __half22float2(*reinterpret_cast<const __half2*>(&vv.z));
            const float2 f3 = __half22float2(*reinterpret_cast<const __half2*>(&vv.w));
            acc0 = ffma2(pk2(f0.x, f0.y), pp, acc0);
            acc1 = ffma2(pk2(f1.x, f1.y), pp, acc1);
            acc2 = ffma2(pk2(f2.x, f2.y), pp, acc2);
            acc3 = ffma2(pk2(f3.x, f3.y), pp, acc3);
        }
        {
            const uint4 vv = vb4[(int)P.z * 16 + j];
            const unsigned long long pp = pk2(__uint_as_float(P.w), __uint_as_float(P.w));
            const float2 f0 = __half22float2(*reinterpret_cast<const __half2*>(&vv.x));
            const float2 f1 = __half22float2(*reinterpret_cast<const __half2*>(&vv.y));
            const float2 f2 = __half22float2(*reinterpret_cast<const __half2*>(&vv.z));
            const float2 f3 = __half22float2(*reinterpret_cast<const __half2*>(&vv.w));
            acc0 = ffma2(pk2(f0.x, f0.y), pp, acc0);
            acc1 = ffma2(pk2(f1.x, f1.y), pp, acc1);
            acc2 = ffma2(pk2(f2.x, f2.y), pp, acc2);
            acc3 = ffma2(pk2(f3.x, f3.y), pp, acc3);
        }
    }

    float r0, r1, r2, r3, r4, r5, r6, r7;
    upk2(acc0, r0, r1);
    upk2(acc1, r2, r3);
    upk2(acc2, r4, r5);
    upk2(acc3, r6, r7);

    // cross-half-warp combine: lane keeps d = 8j + 4h + 0..3
    float keep[4], other[4];
    if (h == 0) {
        keep[0] = r0; keep[1] = r1; keep[2] = r2; keep[3] = r3;
        other[0] = r4; other[1] = r5; other[2] = r6; other[3] = r7;
    } else {
        keep[0] = r4; keep[1] = r5; keep[2] = r6; keep[3] = r7;
        other[0] = r0; other[1] = r1; other[2] = r2; other[3] = r3;
    }
#pragma unroll
    for (int i = 0; i < 4; i++) {
        const float recv = __shfl_xor_sync(0xffffffffu, other[i], 16);
        keep[i] = (keep[i] + recv) * inv;
    }

    float4 res = make_float4(keep[0], keep[1], keep[2], keep[3]);
    *reinterpret_cast<float4*>(out + (size_t)gw * DD + 8 * j + 4 * h) = res;
}

extern "C" void kernel_launch(void* const* d_in, const int* in_sizes, int n_in,
                              void* d_out, int out_size)
{
    const float* q   = (const float*)d_in[0];
    const float* k   = (const float*)d_in[1];
    const float* v   = (const float*)d_in[2];
    const int*   col = (const int*)d_in[3];
    float*       out = (float*)d_out;

    cvt_kernel<<<TOT_F4 / 256, 256>>>((const float4*)k, (const float4*)v);

    const int blocks = (BH * NN) / WARPS_PER_BLOCK;   // 6144
    sparse_core_attention_kernel<<<blocks, THREADS_PER_BLOCK>>>(q, col, out);
}